// round 1
// baseline (speedup 1.0000x reference)
#include <cuda_runtime.h>
#include <math.h>

#define NB      8
#define NSEQ    256
#define DIMC    512
#define NHEADS  8
#define DH      64
#define NTOK    (NB * NSEQ)       // 2048
#define QKV3    (3 * DIMC)        // 1536
#define SCALE   0.125f            // 64^-0.5

// ---------------- scratch (no cudaMalloc allowed) ----------------
__device__ float g_xn[NTOK * DIMC];                      // 4 MB
__device__ float g_qkv[NTOK * QKV3];                     // 12.6 MB
__device__ float g_attn[NB * NHEADS * NSEQ * NSEQ];      // 16.8 MB  [b][h][n][m]
__device__ float g_o[NTOK * DIMC];                       // 4 MB     [b][n][h*64+d]

// =================================================================
// LayerNorm: one block per (b,n) row, 256 threads, 2 elems/thread
// =================================================================
__global__ void ln_kernel(const float* __restrict__ x,
                          const float* __restrict__ gamma,
                          const float* __restrict__ beta) {
  int row = blockIdx.x;
  int t = threadIdx.x;
  const float* xr = x + (size_t)row * DIMC;
  float v0 = xr[t], v1 = xr[t + 256];

  __shared__ float red[8];
  __shared__ float stat;

  // mean
  float s = v0 + v1;
  #pragma unroll
  for (int o = 16; o; o >>= 1) s += __shfl_xor_sync(0xffffffffu, s, o);
  if ((t & 31) == 0) red[t >> 5] = s;
  __syncthreads();
  if (t < 32) {
    float z = (t < 8) ? red[t] : 0.f;
    #pragma unroll
    for (int o = 4; o; o >>= 1) z += __shfl_xor_sync(0xffffffffu, z, o);
    if (t == 0) stat = z * (1.f / DIMC);
  }
  __syncthreads();
  float mean = stat;
  __syncthreads();

  // variance
  float d0 = v0 - mean, d1 = v1 - mean;
  float vs = d0 * d0 + d1 * d1;
  #pragma unroll
  for (int o = 16; o; o >>= 1) vs += __shfl_xor_sync(0xffffffffu, vs, o);
  if ((t & 31) == 0) red[t >> 5] = vs;
  __syncthreads();
  if (t < 32) {
    float z = (t < 8) ? red[t] : 0.f;
    #pragma unroll
    for (int o = 4; o; o >>= 1) z += __shfl_xor_sync(0xffffffffu, z, o);
    if (t == 0) stat = rsqrtf(z * (1.f / DIMC) + 1e-5f);
  }
  __syncthreads();
  float inv = stat;

  float* xo = g_xn + (size_t)row * DIMC;
  xo[t]       = d0 * inv * gamma[t]       + beta[t];
  xo[t + 256] = d1 * inv * gamma[t + 256] + beta[t + 256];
}

// =================================================================
// SIMT fp32 GEMM: C[M,N] = A[M,K] @ B[K,N] (+ bias)
// BM=128, BN=64, BK=16, 256 threads, 8x4 per thread
// =================================================================
__global__ __launch_bounds__(256) void gemm_kernel(
    const float* __restrict__ A, const float* __restrict__ B,
    const float* __restrict__ bias, float* __restrict__ C,
    int M, int N, int K) {
  __shared__ float As[16][132];   // transposed A tile, padded
  __shared__ float Bs[16][64];

  int t = threadIdx.x;
  int bm = blockIdx.y * 128, bn = blockIdx.x * 64;
  int tx = t & 15, ty = t >> 4;

  float acc[8][4];
  #pragma unroll
  for (int i = 0; i < 8; ++i)
    #pragma unroll
    for (int j = 0; j < 4; ++j) acc[i][j] = 0.f;

  int ar = t >> 2;            // 0..63
  int ak = (t & 3) * 4;       // 0,4,8,12
  int bk = t >> 4;            // 0..15
  int bn4 = (t & 15) * 4;

  for (int k0 = 0; k0 < K; k0 += 16) {
    #pragma unroll
    for (int i = 0; i < 2; ++i) {
      int r = ar + i * 64;
      float4 a4 = *(const float4*)&A[(size_t)(bm + r) * K + k0 + ak];
      As[ak + 0][r] = a4.x; As[ak + 1][r] = a4.y;
      As[ak + 2][r] = a4.z; As[ak + 3][r] = a4.w;
    }
    float4 b4 = *(const float4*)&B[(size_t)(k0 + bk) * N + bn + bn4];
    *(float4*)&Bs[bk][bn4] = b4;
    __syncthreads();

    #pragma unroll
    for (int kk = 0; kk < 16; ++kk) {
      float4 a0 = *(const float4*)&As[kk][ty * 8];
      float4 a1 = *(const float4*)&As[kk][ty * 8 + 4];
      float4 bb = *(const float4*)&Bs[kk][tx * 4];
      float av[8] = {a0.x, a0.y, a0.z, a0.w, a1.x, a1.y, a1.z, a1.w};
      float bv[4] = {bb.x, bb.y, bb.z, bb.w};
      #pragma unroll
      for (int i = 0; i < 8; ++i)
        #pragma unroll
        for (int j = 0; j < 4; ++j) acc[i][j] += av[i] * bv[j];
    }
    __syncthreads();
  }

  float bx = 0.f, by = 0.f, bz = 0.f, bw = 0.f;
  if (bias) {
    bx = bias[bn + tx * 4 + 0]; by = bias[bn + tx * 4 + 1];
    bz = bias[bn + tx * 4 + 2]; bw = bias[bn + tx * 4 + 3];
  }
  #pragma unroll
  for (int i = 0; i < 8; ++i) {
    float4 o;
    o.x = acc[i][0] + bx; o.y = acc[i][1] + by;
    o.z = acc[i][2] + bz; o.w = acc[i][3] + bw;
    *(float4*)&C[(size_t)(bm + ty * 8 + i) * N + bn + tx * 4] = o;
  }
}

// =================================================================
// Fused attention per (b, h, 64-row n-tile):
//   scores = scale * Q Kᵀ ; softmax ; attn -> g_attn ; out1 = attn V -> g_o
// Dynamic smem: Ks[64][256] (d-major) + Vs[256][64] + Qs[64][64] (d-major)
//             + Ps[64][260]  = 214016 bytes
// =================================================================
#define ATTN_SMEM_BYTES ((64 * 256 + 256 * 64 + 64 * 64 + 64 * 260) * 4)

__global__ __launch_bounds__(256, 1) void attn_kernel() {
  extern __shared__ float sm[];
  float* Ks = sm;                 // [d][m] 64x256
  float* Vs = Ks + 64 * 256;      // [m][d] 256x64
  float* Qs = Vs + 256 * 64;      // [d][n] 64x64
  float* Ps = Qs + 64 * 64;       // [n][260]

  int t = threadIdx.x;
  int b = blockIdx.y >> 3, h = blockIdx.y & 7;
  int n0 = blockIdx.x * 64;

  int c16 = t & 15, r16 = t >> 4;
  int d0 = c16 * 4;
  const float* qkvb = g_qkv + (size_t)b * NSEQ * QKV3 + h * DH;

  // stage K (transposed), V
  #pragma unroll
  for (int i = 0; i < 16; ++i) {
    int m = r16 + i * 16;
    const float* rowp = qkvb + (size_t)m * QKV3;
    float4 k4 = *(const float4*)(rowp + DIMC + d0);
    Ks[(d0 + 0) * 256 + m] = k4.x; Ks[(d0 + 1) * 256 + m] = k4.y;
    Ks[(d0 + 2) * 256 + m] = k4.z; Ks[(d0 + 3) * 256 + m] = k4.w;
    float4 v4 = *(const float4*)(rowp + 2 * DIMC + d0);
    *(float4*)&Vs[m * 64 + d0] = v4;
  }
  // stage Q (transposed)
  #pragma unroll
  for (int i = 0; i < 4; ++i) {
    int n = r16 + i * 16;
    const float* rowp = qkvb + (size_t)(n0 + n) * QKV3;
    float4 q4 = *(const float4*)(rowp + d0);
    Qs[(d0 + 0) * 64 + n] = q4.x; Qs[(d0 + 1) * 64 + n] = q4.y;
    Qs[(d0 + 2) * 64 + n] = q4.z; Qs[(d0 + 3) * 64 + n] = q4.w;
  }
  __syncthreads();

  // ---- scores: 64x256 = Qtile(64x64) @ K(64x256)ᵀ, 8x8 per thread ----
  {
    int tm = t & 31, tn = t >> 5;
    float acc[8][8];
    #pragma unroll
    for (int i = 0; i < 8; ++i)
      #pragma unroll
      for (int j = 0; j < 8; ++j) acc[i][j] = 0.f;

    for (int d = 0; d < 64; ++d) {
      const float* qrow = &Qs[d * 64 + tn * 8];
      float4 qa = *(const float4*)qrow;
      float4 qb = *(const float4*)(qrow + 4);
      const float* krow = &Ks[d * 256];
      float4 ka = *(const float4*)(krow + tm * 4);          // m = tm*4..+3
      float4 kb = *(const float4*)(krow + 128 + tm * 4);    // m = 128+tm*4..+3
      float qv[8] = {qa.x, qa.y, qa.z, qa.w, qb.x, qb.y, qb.z, qb.w};
      float kv[8] = {ka.x, ka.y, ka.z, ka.w, kb.x, kb.y, kb.z, kb.w};
      #pragma unroll
      for (int i = 0; i < 8; ++i)
        #pragma unroll
        for (int j = 0; j < 8; ++j) acc[i][j] += qv[i] * kv[j];
    }
    #pragma unroll
    for (int i = 0; i < 8; ++i) {
      int n = tn * 8 + i;
      float4 o1 = {acc[i][0] * SCALE, acc[i][1] * SCALE,
                   acc[i][2] * SCALE, acc[i][3] * SCALE};
      float4 o2 = {acc[i][4] * SCALE, acc[i][5] * SCALE,
                   acc[i][6] * SCALE, acc[i][7] * SCALE};
      *(float4*)&Ps[n * 260 + tm * 4] = o1;
      *(float4*)&Ps[n * 260 + 128 + tm * 4] = o2;
    }
  }
  __syncthreads();

  // ---- softmax per row; write normalized attn to smem + global ----
  {
    int w = t >> 5, l = t & 31;
    #pragma unroll
    for (int r = 0; r < 8; ++r) {
      int n = w * 8 + r;
      float* row = &Ps[n * 260];
      float vals[8];
      float vmax = -1e30f;
      #pragma unroll
      for (int i = 0; i < 8; ++i) {
        vals[i] = row[l + i * 32];
        vmax = fmaxf(vmax, vals[i]);
      }
      #pragma unroll
      for (int o = 16; o; o >>= 1)
        vmax = fmaxf(vmax, __shfl_xor_sync(0xffffffffu, vmax, o));
      float ssum = 0.f;
      #pragma unroll
      for (int i = 0; i < 8; ++i) { vals[i] = __expf(vals[i] - vmax); ssum += vals[i]; }
      #pragma unroll
      for (int o = 16; o; o >>= 1) ssum += __shfl_xor_sync(0xffffffffu, ssum, o);
      float inv = 1.f / ssum;
      float* gA = &g_attn[((size_t)(b * 8 + h) * 256 + n0 + n) * 256];
      #pragma unroll
      for (int i = 0; i < 8; ++i) {
        float a = vals[i] * inv;
        row[l + i * 32] = a;
        gA[l + i * 32] = a;
      }
    }
  }
  __syncthreads();

  // ---- out1 = P(64x256) @ V(256x64), 4x4 per thread ----
  {
    int td = t & 15, tn2 = t >> 4;
    float oc[4][4];
    #pragma unroll
    for (int i = 0; i < 4; ++i)
      #pragma unroll
      for (int j = 0; j < 4; ++j) oc[i][j] = 0.f;

    for (int m = 0; m < 256; m += 4) {
      float4 vv0 = *(const float4*)&Vs[(m + 0) * 64 + td * 4];
      float4 vv1 = *(const float4*)&Vs[(m + 1) * 64 + td * 4];
      float4 vv2 = *(const float4*)&Vs[(m + 2) * 64 + td * 4];
      float4 vv3 = *(const float4*)&Vs[(m + 3) * 64 + td * 4];
      #pragma unroll
      for (int i = 0; i < 4; ++i) {
        float4 p = *(const float4*)&Ps[(tn2 * 4 + i) * 260 + m];
        oc[i][0] += p.x * vv0.x + p.y * vv1.x + p.z * vv2.x + p.w * vv3.x;
        oc[i][1] += p.x * vv0.y + p.y * vv1.y + p.z * vv2.y + p.w * vv3.y;
        oc[i][2] += p.x * vv0.z + p.y * vv1.z + p.z * vv2.z + p.w * vv3.z;
        oc[i][3] += p.x * vv0.w + p.y * vv1.w + p.z * vv2.w + p.w * vv3.w;
      }
    }
    #pragma unroll
    for (int i = 0; i < 4; ++i) {
      float4 o = {oc[i][0], oc[i][1], oc[i][2], oc[i][3]};
      *(float4*)&g_o[(size_t)(b * 256 + n0 + tn2 * 4 + i) * 512 + h * 64 + td * 4] = o;
    }
  }
}

// =================================================================
// rpos: out2[b,h,n,d] += Σ_m attn[b,h,n,m] * T[idx[n,m], h*64+d]
// Block = (n, h); 8 warps each own an m-chunk of 32 and serve ALL 8
// batches per table-row load (8x fewer L1 wavefronts than per-b gather).
// =================================================================
__global__ __launch_bounds__(256) void rpos_kernel(
    const float* __restrict__ table, const int* __restrict__ idx_map) {
  int n = blockIdx.x, h = blockIdx.y;
  __shared__ float sA[8][256];
  __shared__ int   sIdx[256];
  __shared__ float sPart[8][8][64];  // [warp][b][d]

  int t = threadIdx.x;
  sIdx[t] = idx_map[n * 256 + t];
  #pragma unroll
  for (int b = 0; b < 8; ++b)
    sA[b][t] = g_attn[((size_t)(b * 8 + h) * 256 + n) * 256 + t];
  __syncthreads();

  int w = t >> 5, l = t & 31;
  float accx[8], accy[8];
  #pragma unroll
  for (int b = 0; b < 8; ++b) { accx[b] = 0.f; accy[b] = 0.f; }

  const float* tb = table + h * DH + 2 * l;
  #pragma unroll 4
  for (int mm = 0; mm < 32; ++mm) {
    int m = w * 32 + mm;
    int p = sIdx[m];
    float2 tv = *(const float2*)&tb[(size_t)p * DIMC];
    #pragma unroll
    for (int b = 0; b < 8; ++b) {
      float a = sA[b][m];
      accx[b] += a * tv.x;
      accy[b] += a * tv.y;
    }
  }
  #pragma unroll
  for (int b = 0; b < 8; ++b) {
    sPart[w][b][2 * l]     = accx[b];
    sPart[w][b][2 * l + 1] = accy[b];
  }
  __syncthreads();

  #pragma unroll
  for (int o = t; o < 512; o += 256) {
    int b = o >> 6, d = o & 63;
    float s2 = 0.f;
    #pragma unroll
    for (int w2 = 0; w2 < 8; ++w2) s2 += sPart[w2][b][d];
    g_o[(size_t)(b * 256 + n) * 512 + h * 64 + d] += s2;
  }
}

// =================================================================
extern "C" void kernel_launch(void* const* d_in, const int* in_sizes, int n_in,
                              void* d_out, int out_size) {
  const float* x      = (const float*)d_in[0];
  const float* ln_g   = (const float*)d_in[1];
  const float* ln_b   = (const float*)d_in[2];
  const float* w_qkv  = (const float*)d_in[3];
  const float* table  = (const float*)d_in[4];
  const float* w_out  = (const float*)d_in[5];
  const float* b_out  = (const float*)d_in[6];
  const int*   idxmap = (const int*)d_in[7];
  float* out = (float*)d_out;

  cudaFuncSetAttribute(attn_kernel, cudaFuncAttributeMaxDynamicSharedMemorySize,
                       ATTN_SMEM_BYTES);

  void *p_xn, *p_qkv, *p_o;
  cudaGetSymbolAddress(&p_xn, g_xn);
  cudaGetSymbolAddress(&p_qkv, g_qkv);
  cudaGetSymbolAddress(&p_o, g_o);

  // 1. LayerNorm
  ln_kernel<<<NTOK, 256>>>(x, ln_g, ln_b);

  // 2. qkv = xn @ w_qkv   (2048 x 1536 x 512)
  gemm_kernel<<<dim3(QKV3 / 64, NTOK / 128), 256>>>(
      (const float*)p_xn, w_qkv, nullptr, (float*)p_qkv, NTOK, QKV3, DIMC);

  // 3. attention (scores, softmax, attn·V)
  attn_kernel<<<dim3(4, NB * NHEADS), 256, ATTN_SMEM_BYTES>>>();

  // 4. relative-position contribution
  rpos_kernel<<<dim3(NSEQ, NHEADS), 256>>>(table, idxmap);

  // 5. out = g_o @ w_out + b_out   (2048 x 512 x 512)
  gemm_kernel<<<dim3(DIMC / 64, NTOK / 128), 256>>>(
      (const float*)p_o, w_out, b_out, out, NTOK, DIMC, DIMC);
}

// round 2
// speedup vs baseline: 2.1189x; 2.1189x over previous
#include <cuda_runtime.h>
#include <math.h>
#include <stdint.h>

#define NB      8
#define NSEQ    256
#define DIMC    512
#define NHEADS  8
#define DH      64
#define NTOK    (NB * NSEQ)       // 2048
#define QKV3    (3 * DIMC)        // 1536
#define SCALE   0.125f            // 64^-0.5

// ---------------- scratch (no cudaMalloc allowed) ----------------
__device__ float g_xn[NTOK * DIMC];                      // 4 MB
__device__ float g_qkv[NTOK * QKV3];                     // 12.6 MB
__device__ float g_attn[NB * NHEADS * NSEQ * NSEQ];      // 16.8 MB  [b][h][n][m]
__device__ float g_o[NTOK * DIMC];                       // 4 MB     [b][n][h*64+d]

// ---------------- tf32 mma helpers ----------------
__device__ __forceinline__ uint32_t f2tf(float x) {
  uint32_t r;
  asm("cvt.rna.tf32.f32 %0, %1;" : "=r"(r) : "f"(x));
  return r;
}

__device__ __forceinline__ void mma_tf32(float c[4],
    uint32_t a0, uint32_t a1, uint32_t a2, uint32_t a3,
    uint32_t b0, uint32_t b1) {
  asm volatile(
    "mma.sync.aligned.m16n8k8.row.col.f32.tf32.tf32.f32 "
    "{%0,%1,%2,%3}, {%4,%5,%6,%7}, {%8,%9}, {%0,%1,%2,%3};\n"
    : "+f"(c[0]), "+f"(c[1]), "+f"(c[2]), "+f"(c[3])
    : "r"(a0), "r"(a1), "r"(a2), "r"(a3), "r"(b0), "r"(b1));
}

// =================================================================
// LayerNorm: one block per (b,n) row, 256 threads, 2 elems/thread
// =================================================================
__global__ void ln_kernel(const float* __restrict__ x,
                          const float* __restrict__ gamma,
                          const float* __restrict__ beta) {
  int row = blockIdx.x;
  int t = threadIdx.x;
  const float* xr = x + (size_t)row * DIMC;
  float v0 = xr[t], v1 = xr[t + 256];

  __shared__ float red[8];
  __shared__ float stat;

  float s = v0 + v1;
  #pragma unroll
  for (int o = 16; o; o >>= 1) s += __shfl_xor_sync(0xffffffffu, s, o);
  if ((t & 31) == 0) red[t >> 5] = s;
  __syncthreads();
  if (t < 32) {
    float z = (t < 8) ? red[t] : 0.f;
    #pragma unroll
    for (int o = 4; o; o >>= 1) z += __shfl_xor_sync(0xffffffffu, z, o);
    if (t == 0) stat = z * (1.f / DIMC);
  }
  __syncthreads();
  float mean = stat;
  __syncthreads();

  float d0 = v0 - mean, d1 = v1 - mean;
  float vs = d0 * d0 + d1 * d1;
  #pragma unroll
  for (int o = 16; o; o >>= 1) vs += __shfl_xor_sync(0xffffffffu, vs, o);
  if ((t & 31) == 0) red[t >> 5] = vs;
  __syncthreads();
  if (t < 32) {
    float z = (t < 8) ? red[t] : 0.f;
    #pragma unroll
    for (int o = 4; o; o >>= 1) z += __shfl_xor_sync(0xffffffffu, z, o);
    if (t == 0) stat = rsqrtf(z * (1.f / DIMC) + 1e-5f);
  }
  __syncthreads();
  float inv = stat;

  float* xo = g_xn + (size_t)row * DIMC;
  xo[t]       = d0 * inv * gamma[t]       + beta[t];
  xo[t + 256] = d1 * inv * gamma[t + 256] + beta[t + 256];
}

// =================================================================
// tf32 tensor-core GEMM: C[M,N] = A[M,K] @ B[K,N] (+bias)
// BM=128, BN=64, BK=16, 128 threads (4 warps, 2x2, warp tile 64x32)
// =================================================================
__global__ __launch_bounds__(128) void gemm_tf32(
    const float* __restrict__ A, const float* __restrict__ B,
    const float* __restrict__ bias, float* __restrict__ C,
    int M, int N, int K) {
  __shared__ uint32_t As[16][132];  // [k][m]
  __shared__ uint32_t Bs[16][68];   // [k][n]

  int t = threadIdx.x;
  int w = t >> 5, l = t & 31;
  int wm = (w >> 1) * 64;
  int wn = (w & 1) * 32;
  int g = l >> 2, tg = l & 3;
  int bm = blockIdx.y * 128, bn = blockIdx.x * 64;

  float c[4][4][4];
  #pragma unroll
  for (int i = 0; i < 4; ++i)
    #pragma unroll
    for (int j = 0; j < 4; ++j)
      #pragma unroll
      for (int q = 0; q < 4; ++q) c[i][j][q] = 0.f;

  for (int k0 = 0; k0 < K; k0 += 16) {
    // stage A transposed: thread t owns row bm+t (16 k values)
    {
      const float* ar = A + (size_t)(bm + t) * K + k0;
      #pragma unroll
      for (int j = 0; j < 4; ++j) {
        float4 v = *(const float4*)(ar + j * 4);
        As[j * 4 + 0][t] = f2tf(v.x); As[j * 4 + 1][t] = f2tf(v.y);
        As[j * 4 + 2][t] = f2tf(v.z); As[j * 4 + 3][t] = f2tf(v.w);
      }
    }
    // stage B natural [k][n]
    {
      int r = t >> 4, cc = (t & 15) * 4;
      #pragma unroll
      for (int j = 0; j < 2; ++j) {
        float4 v = *(const float4*)(B + (size_t)(k0 + r + j * 8) * N + bn + cc);
        Bs[r + j * 8][cc + 0] = f2tf(v.x); Bs[r + j * 8][cc + 1] = f2tf(v.y);
        Bs[r + j * 8][cc + 2] = f2tf(v.z); Bs[r + j * 8][cc + 3] = f2tf(v.w);
      }
    }
    __syncthreads();

    #pragma unroll
    for (int kk = 0; kk < 16; kk += 8) {
      uint32_t a[4][4], bf[4][2];
      #pragma unroll
      for (int i = 0; i < 4; ++i) {
        int m0 = wm + i * 16;
        a[i][0] = As[kk + tg][m0 + g];
        a[i][1] = As[kk + tg][m0 + g + 8];
        a[i][2] = As[kk + tg + 4][m0 + g];
        a[i][3] = As[kk + tg + 4][m0 + g + 8];
      }
      #pragma unroll
      for (int j = 0; j < 4; ++j) {
        int n0 = wn + j * 8;
        bf[j][0] = Bs[kk + tg][n0 + g];
        bf[j][1] = Bs[kk + tg + 4][n0 + g];
      }
      #pragma unroll
      for (int i = 0; i < 4; ++i)
        #pragma unroll
        for (int j = 0; j < 4; ++j)
          mma_tf32(c[i][j], a[i][0], a[i][1], a[i][2], a[i][3],
                   bf[j][0], bf[j][1]);
    }
    __syncthreads();
  }

  #pragma unroll
  for (int i = 0; i < 4; ++i) {
    int row0 = bm + wm + i * 16 + g;
    #pragma unroll
    for (int j = 0; j < 4; ++j) {
      int col = bn + wn + j * 8 + tg * 2;
      float b0 = bias ? bias[col] : 0.f;
      float b1 = bias ? bias[col + 1] : 0.f;
      float2 v0 = {c[i][j][0] + b0, c[i][j][1] + b1};
      float2 v1 = {c[i][j][2] + b0, c[i][j][3] + b1};
      *(float2*)&C[(size_t)row0 * N + col] = v0;
      *(float2*)&C[(size_t)(row0 + 8) * N + col] = v1;
    }
  }
}

// =================================================================
// Fused attention per (b, h, 64-row n-tile), tf32 mma for QK^T and PV
// smem: Qs u32[64][68] + Ks u32[256][68] + Vt u32[64][264] + Ps f32[64][260]
// =================================================================
#define QS_OFF  0
#define KS_OFF  (64 * 68)
#define VT_OFF  (KS_OFF + 256 * 68)
#define PS_OFF  (VT_OFF + 64 * 264)
#define ATTN_SMEM_WORDS (PS_OFF + 64 * 260)
#define ATTN_SMEM_BYTES (ATTN_SMEM_WORDS * 4)

__global__ __launch_bounds__(256, 1) void attn_kernel() {
  extern __shared__ uint32_t sm[];
  uint32_t* Qs = sm + QS_OFF;     // [n][d]  stride 68
  uint32_t* Ks = sm + KS_OFF;     // [m][d]  stride 68
  uint32_t* Vt = sm + VT_OFF;     // [d][m]  stride 264
  float*    Ps = (float*)(sm + PS_OFF);  // [n][m] stride 260
  uint32_t* PsU = sm + PS_OFF;

  int t = threadIdx.x;
  int b = blockIdx.y >> 3, h = blockIdx.y & 7;
  int n0 = blockIdx.x * 64;
  int w = t >> 5, l = t & 31;
  int g = l >> 2, tg = l & 3;

  const float* qkvb = g_qkv + (size_t)b * NSEQ * QKV3 + h * DH;

  // ---- stage K [m][d], V transposed [d][m], Q [n][d] (tf32) ----
  {
    int c16 = t & 15, r16 = t >> 4;
    int d0 = c16 * 4;
    #pragma unroll
    for (int i = 0; i < 16; ++i) {
      int m = r16 + i * 16;
      const float* rowp = qkvb + (size_t)m * QKV3;
      float4 k4 = *(const float4*)(rowp + DIMC + d0);
      uint4 ku = {f2tf(k4.x), f2tf(k4.y), f2tf(k4.z), f2tf(k4.w)};
      *(uint4*)&Ks[m * 68 + d0] = ku;
      float4 v4 = *(const float4*)(rowp + 2 * DIMC + d0);
      Vt[(d0 + 0) * 264 + m] = f2tf(v4.x);
      Vt[(d0 + 1) * 264 + m] = f2tf(v4.y);
      Vt[(d0 + 2) * 264 + m] = f2tf(v4.z);
      Vt[(d0 + 3) * 264 + m] = f2tf(v4.w);
    }
    #pragma unroll
    for (int i = 0; i < 4; ++i) {
      int n = r16 + i * 16;
      const float* rowp = qkvb + (size_t)(n0 + n) * QKV3;
      float4 q4 = *(const float4*)(rowp + d0);
      uint4 qu = {f2tf(q4.x), f2tf(q4.y), f2tf(q4.z), f2tf(q4.w)};
      *(uint4*)&Qs[n * 68 + d0] = qu;
    }
  }
  __syncthreads();

  // ---- scores S[64][256] = Q @ K^T via mma; warp tile 32x64 ----
  {
    int wm = (w >> 2) * 32;   // n rows
    int wnn = (w & 3) * 64;   // m cols
    float s[2][8][4];
    #pragma unroll
    for (int i = 0; i < 2; ++i)
      #pragma unroll
      for (int j = 0; j < 8; ++j)
        #pragma unroll
        for (int q = 0; q < 4; ++q) s[i][j][q] = 0.f;

    #pragma unroll
    for (int kk = 0; kk < 64; kk += 8) {
      uint32_t a[2][4], bf[8][2];
      #pragma unroll
      for (int i = 0; i < 2; ++i) {
        int r0 = wm + i * 16;
        a[i][0] = Qs[(r0 + g) * 68 + kk + tg];
        a[i][1] = Qs[(r0 + g + 8) * 68 + kk + tg];
        a[i][2] = Qs[(r0 + g) * 68 + kk + tg + 4];
        a[i][3] = Qs[(r0 + g + 8) * 68 + kk + tg + 4];
      }
      #pragma unroll
      for (int j = 0; j < 8; ++j) {
        int m0 = wnn + j * 8;
        bf[j][0] = Ks[(m0 + g) * 68 + kk + tg];
        bf[j][1] = Ks[(m0 + g) * 68 + kk + tg + 4];
      }
      #pragma unroll
      for (int i = 0; i < 2; ++i)
        #pragma unroll
        for (int j = 0; j < 8; ++j)
          mma_tf32(s[i][j], a[i][0], a[i][1], a[i][2], a[i][3],
                   bf[j][0], bf[j][1]);
    }
    // write scaled scores to Ps (fp32)
    #pragma unroll
    for (int i = 0; i < 2; ++i) {
      int r0 = wm + i * 16 + g;
      #pragma unroll
      for (int j = 0; j < 8; ++j) {
        int cc = wnn + j * 8 + tg * 2;
        Ps[r0 * 260 + cc]           = s[i][j][0] * SCALE;
        Ps[r0 * 260 + cc + 1]       = s[i][j][1] * SCALE;
        Ps[(r0 + 8) * 260 + cc]     = s[i][j][2] * SCALE;
        Ps[(r0 + 8) * 260 + cc + 1] = s[i][j][3] * SCALE;
      }
    }
  }
  __syncthreads();

  // ---- softmax per row; fp32 attn -> g_attn, tf32 bits -> Ps in place ----
  {
    #pragma unroll
    for (int r = 0; r < 8; ++r) {
      int n = w * 8 + r;
      float* row = &Ps[n * 260];
      float vals[8];
      float vmax = -1e30f;
      #pragma unroll
      for (int i = 0; i < 8; ++i) {
        vals[i] = row[l + i * 32];
        vmax = fmaxf(vmax, vals[i]);
      }
      #pragma unroll
      for (int o = 16; o; o >>= 1)
        vmax = fmaxf(vmax, __shfl_xor_sync(0xffffffffu, vmax, o));
      float ssum = 0.f;
      #pragma unroll
      for (int i = 0; i < 8; ++i) { vals[i] = __expf(vals[i] - vmax); ssum += vals[i]; }
      #pragma unroll
      for (int o = 16; o; o >>= 1) ssum += __shfl_xor_sync(0xffffffffu, ssum, o);
      float inv = 1.f / ssum;
      float* gA = &g_attn[((size_t)(b * 8 + h) * 256 + n0 + n) * 256];
      #pragma unroll
      for (int i = 0; i < 8; ++i) {
        float a = vals[i] * inv;
        gA[l + i * 32] = a;
        PsU[n * 260 + l + i * 32] = f2tf(a);
      }
    }
  }
  __syncthreads();

  // ---- O[64][64] = P @ V via mma; warp tile 32x16 ----
  {
    int wm = (w >> 2) * 32;   // n rows
    int wd = (w & 3) * 16;    // d cols
    float oc[2][2][4];
    #pragma unroll
    for (int i = 0; i < 2; ++i)
      #pragma unroll
      for (int j = 0; j < 2; ++j)
        #pragma unroll
        for (int q = 0; q < 4; ++q) oc[i][j][q] = 0.f;

    #pragma unroll 4
    for (int kk = 0; kk < 256; kk += 8) {
      uint32_t a[2][4], bf[2][2];
      #pragma unroll
      for (int i = 0; i < 2; ++i) {
        int r0 = wm + i * 16;
        a[i][0] = PsU[(r0 + g) * 260 + kk + tg];
        a[i][1] = PsU[(r0 + g + 8) * 260 + kk + tg];
        a[i][2] = PsU[(r0 + g) * 260 + kk + tg + 4];
        a[i][3] = PsU[(r0 + g + 8) * 260 + kk + tg + 4];
      }
      #pragma unroll
      for (int j = 0; j < 2; ++j) {
        int d0 = wd + j * 8;
        bf[j][0] = Vt[(d0 + g) * 264 + kk + tg];
        bf[j][1] = Vt[(d0 + g) * 264 + kk + tg + 4];
      }
      #pragma unroll
      for (int i = 0; i < 2; ++i)
        #pragma unroll
        for (int j = 0; j < 2; ++j)
          mma_tf32(oc[i][j], a[i][0], a[i][1], a[i][2], a[i][3],
                   bf[j][0], bf[j][1]);
    }
    #pragma unroll
    for (int i = 0; i < 2; ++i) {
      int n = n0 + wm + i * 16 + g;
      #pragma unroll
      for (int j = 0; j < 2; ++j) {
        int dd = h * 64 + wd + j * 8 + tg * 2;
        float2 v0 = {oc[i][j][0], oc[i][j][1]};
        float2 v1 = {oc[i][j][2], oc[i][j][3]};
        *(float2*)&g_o[(size_t)(b * 256 + n) * 512 + dd] = v0;
        *(float2*)&g_o[(size_t)(b * 256 + n + 8) * 512 + dd] = v1;
      }
    }
  }
}

// =================================================================
// rpos: out2[b,h,n,d] += Σ_m attn[b,h,n,m] * T[idx[n,m], h*64+d]
// =================================================================
__global__ __launch_bounds__(256) void rpos_kernel(
    const float* __restrict__ table, const int* __restrict__ idx_map) {
  int n = blockIdx.x, h = blockIdx.y;
  __shared__ float sA[8][256];
  __shared__ int   sIdx[256];
  __shared__ float sPart[8][8][64];  // [warp][b][d]

  int t = threadIdx.x;
  sIdx[t] = idx_map[n * 256 + t];
  #pragma unroll
  for (int b = 0; b < 8; ++b)
    sA[b][t] = g_attn[((size_t)(b * 8 + h) * 256 + n) * 256 + t];
  __syncthreads();

  int w = t >> 5, l = t & 31;
  float accx[8], accy[8];
  #pragma unroll
  for (int b = 0; b < 8; ++b) { accx[b] = 0.f; accy[b] = 0.f; }

  const float* tb = table + h * DH + 2 * l;
  #pragma unroll 4
  for (int mm = 0; mm < 32; ++mm) {
    int m = w * 32 + mm;
    int p = sIdx[m];
    float2 tv = *(const float2*)&tb[(size_t)p * DIMC];
    #pragma unroll
    for (int b = 0; b < 8; ++b) {
      float a = sA[b][m];
      accx[b] += a * tv.x;
      accy[b] += a * tv.y;
    }
  }
  #pragma unroll
  for (int b = 0; b < 8; ++b) {
    sPart[w][b][2 * l]     = accx[b];
    sPart[w][b][2 * l + 1] = accy[b];
  }
  __syncthreads();

  #pragma unroll
  for (int o = t; o < 512; o += 256) {
    int b = o >> 6, d = o & 63;
    float s2 = 0.f;
    #pragma unroll
    for (int w2 = 0; w2 < 8; ++w2) s2 += sPart[w2][b][d];
    g_o[(size_t)(b * 256 + n) * 512 + h * 64 + d] += s2;
  }
}

// =================================================================
extern "C" void kernel_launch(void* const* d_in, const int* in_sizes, int n_in,
                              void* d_out, int out_size) {
  const float* x      = (const float*)d_in[0];
  const float* ln_g   = (const float*)d_in[1];
  const float* ln_b   = (const float*)d_in[2];
  const float* w_qkv  = (const float*)d_in[3];
  const float* table  = (const float*)d_in[4];
  const float* w_out  = (const float*)d_in[5];
  const float* b_out  = (const float*)d_in[6];
  const int*   idxmap = (const int*)d_in[7];
  float* out = (float*)d_out;

  cudaFuncSetAttribute(attn_kernel, cudaFuncAttributeMaxDynamicSharedMemorySize,
                       ATTN_SMEM_BYTES);

  void *p_xn, *p_qkv, *p_o;
  cudaGetSymbolAddress(&p_xn, g_xn);
  cudaGetSymbolAddress(&p_qkv, g_qkv);
  cudaGetSymbolAddress(&p_o, g_o);

  // 1. LayerNorm
  ln_kernel<<<NTOK, 256>>>(x, ln_g, ln_b);

  // 2. qkv = xn @ w_qkv   (2048 x 1536 x 512)
  gemm_tf32<<<dim3(QKV3 / 64, NTOK / 128), 128>>>(
      (const float*)p_xn, w_qkv, nullptr, (float*)p_qkv, NTOK, QKV3, DIMC);

  // 3. attention (scores, softmax, attn·V) on tensor cores
  attn_kernel<<<dim3(4, NB * NHEADS), 256, ATTN_SMEM_BYTES>>>();

  // 4. relative-position contribution
  rpos_kernel<<<dim3(NSEQ, NHEADS), 256>>>(table, idxmap);

  // 5. out = g_o @ w_out + b_out   (2048 x 512 x 512)
  gemm_tf32<<<dim3(DIMC / 64, NTOK / 128), 128>>>(
      (const float*)p_o, w_out, b_out, out, NTOK, DIMC, DIMC);
}

// round 3
// speedup vs baseline: 2.6658x; 1.2581x over previous
#include <cuda_runtime.h>
#include <math.h>
#include <stdint.h>

#define NB      8
#define NSEQ    256
#define DIMC    512
#define NHEADS  8
#define DH      64
#define NTOK    (NB * NSEQ)       // 2048
#define QKV3    (3 * DIMC)        // 1536
#define SCALE   0.125f            // 64^-0.5

// ---------------- scratch (no cudaMalloc allowed) ----------------
__device__ float g_xn[NTOK * DIMC];                      // 4 MB
__device__ float g_qkv[NTOK * QKV3];                     // 12.6 MB
__device__ float g_attn[NB * NHEADS * NSEQ * NSEQ];      // 16.8 MB  [b][h][n][m]
__device__ float g_o[NTOK * DIMC];                       // 4 MB     [b][n][h*64+d]

// ---------------- tf32 mma helpers ----------------
__device__ __forceinline__ uint32_t f2tf(float x) {
  uint32_t r;
  asm("cvt.rna.tf32.f32 %0, %1;" : "=r"(r) : "f"(x));
  return r;
}

__device__ __forceinline__ void mma_tf32(float c[4],
    uint32_t a0, uint32_t a1, uint32_t a2, uint32_t a3,
    uint32_t b0, uint32_t b1) {
  asm volatile(
    "mma.sync.aligned.m16n8k8.row.col.f32.tf32.tf32.f32 "
    "{%0,%1,%2,%3}, {%4,%5,%6,%7}, {%8,%9}, {%0,%1,%2,%3};\n"
    : "+f"(c[0]), "+f"(c[1]), "+f"(c[2]), "+f"(c[3])
    : "r"(a0), "r"(a1), "r"(a2), "r"(a3), "r"(b0), "r"(b1));
}

// =================================================================
// LayerNorm: one block per (b,n) row, 256 threads, 2 elems/thread
// =================================================================
__global__ void ln_kernel(const float* __restrict__ x,
                          const float* __restrict__ gamma,
                          const float* __restrict__ beta) {
  int row = blockIdx.x;
  int t = threadIdx.x;
  const float* xr = x + (size_t)row * DIMC;
  float v0 = xr[t], v1 = xr[t + 256];

  __shared__ float red[8];
  __shared__ float stat;

  float s = v0 + v1;
  #pragma unroll
  for (int o = 16; o; o >>= 1) s += __shfl_xor_sync(0xffffffffu, s, o);
  if ((t & 31) == 0) red[t >> 5] = s;
  __syncthreads();
  if (t < 32) {
    float z = (t < 8) ? red[t] : 0.f;
    #pragma unroll
    for (int o = 4; o; o >>= 1) z += __shfl_xor_sync(0xffffffffu, z, o);
    if (t == 0) stat = z * (1.f / DIMC);
  }
  __syncthreads();
  float mean = stat;
  __syncthreads();

  float d0 = v0 - mean, d1 = v1 - mean;
  float vs = d0 * d0 + d1 * d1;
  #pragma unroll
  for (int o = 16; o; o >>= 1) vs += __shfl_xor_sync(0xffffffffu, vs, o);
  if ((t & 31) == 0) red[t >> 5] = vs;
  __syncthreads();
  if (t < 32) {
    float z = (t < 8) ? red[t] : 0.f;
    #pragma unroll
    for (int o = 4; o; o >>= 1) z += __shfl_xor_sync(0xffffffffu, z, o);
    if (t == 0) stat = rsqrtf(z * (1.f / DIMC) + 1e-5f);
  }
  __syncthreads();
  float inv = stat;

  float* xo = g_xn + (size_t)row * DIMC;
  xo[t]       = d0 * inv * gamma[t]       + beta[t];
  xo[t + 256] = d1 * inv * gamma[t + 256] + beta[t + 256];
}

// =================================================================
// tf32 tensor-core GEMM v2: C[M,N] = A[M,K] @ B[K,N] (+bias)
// BM=128, BN template (128 or 64), BK=16, 256 threads,
// double-buffered smem, reg-prefetched global loads, 1 sync/iter.
// =================================================================
template<int BN, int WARPS_M, int WARPS_N>
__global__ __launch_bounds__(256) void gemm_tf32(
    const float* __restrict__ A, const float* __restrict__ B,
    const float* __restrict__ bias, float* __restrict__ C,
    int M, int N, int K) {
  constexpr int BM = 128, BK = 16;
  constexpr int WTM = BM / WARPS_M;
  constexpr int WTN = BN / WARPS_N;
  constexpr int MI = WTM / 16;
  constexpr int NI = WTN / 8;
  constexpr int AS = BK + 4;     // 20 words, conflict-free for A frags
  constexpr int BS = BN + 4;     // conflict-free for B frags
  constexpr int BF4 = (BK * BN) / (256 * 4);  // float4 per thread for B

  __shared__ uint32_t As[2][BM * AS];
  __shared__ uint32_t Bs[2][BK * BS];

  int t = threadIdx.x;
  int w = t >> 5, l = t & 31;
  int g = l >> 2, tg = l & 3;
  int wm = (w % WARPS_M) * WTM;
  int wn = (w / WARPS_M) * WTN;
  int bm = blockIdx.y * BM, bn = blockIdx.x * BN;

  int arow = t >> 1, akh = (t & 1) * 8;
  const float* Aptr = A + (size_t)(bm + arow) * K + akh;

  int brow[BF4], bcol[BF4];
  #pragma unroll
  for (int j = 0; j < BF4; ++j) {
    int lin = (j * 256 + t) * 4;
    brow[j] = lin / BN;
    bcol[j] = lin % BN;
  }

  float c[MI][NI][4];
  #pragma unroll
  for (int i = 0; i < MI; ++i)
    #pragma unroll
    for (int j = 0; j < NI; ++j)
      #pragma unroll
      for (int q = 0; q < 4; ++q) c[i][j][q] = 0.f;

  float4 av0, av1, bv[BF4];

  // prologue: tile 0 -> buffer 0
  av0 = *(const float4*)(Aptr);
  av1 = *(const float4*)(Aptr + 4);
  #pragma unroll
  for (int j = 0; j < BF4; ++j)
    bv[j] = *(const float4*)(B + (size_t)brow[j] * N + bn + bcol[j]);
  {
    uint32_t* as = As[0] + arow * AS + akh;
    as[0]=f2tf(av0.x); as[1]=f2tf(av0.y); as[2]=f2tf(av0.z); as[3]=f2tf(av0.w);
    as[4]=f2tf(av1.x); as[5]=f2tf(av1.y); as[6]=f2tf(av1.z); as[7]=f2tf(av1.w);
    #pragma unroll
    for (int j = 0; j < BF4; ++j) {
      uint32_t* bs = Bs[0] + brow[j] * BS + bcol[j];
      bs[0]=f2tf(bv[j].x); bs[1]=f2tf(bv[j].y); bs[2]=f2tf(bv[j].z); bs[3]=f2tf(bv[j].w);
    }
  }
  __syncthreads();

  int nk = K / BK;
  for (int it = 0; it < nk; ++it) {
    int buf = it & 1;
    bool more = (it + 1 < nk);
    if (more) {
      int k0 = (it + 1) * BK;
      av0 = *(const float4*)(Aptr + k0);
      av1 = *(const float4*)(Aptr + k0 + 4);
      #pragma unroll
      for (int j = 0; j < BF4; ++j)
        bv[j] = *(const float4*)(B + (size_t)(k0 + brow[j]) * N + bn + bcol[j]);
    }

    #pragma unroll
    for (int kk = 0; kk < BK; kk += 8) {
      uint32_t af[MI][4], bf[NI][2];
      #pragma unroll
      for (int i = 0; i < MI; ++i) {
        const uint32_t* p = As[buf] + (wm + i * 16 + g) * AS + kk + tg;
        af[i][0] = p[0];
        af[i][1] = p[8 * AS];
        af[i][2] = p[4];
        af[i][3] = p[8 * AS + 4];
      }
      #pragma unroll
      for (int j = 0; j < NI; ++j) {
        const uint32_t* p = Bs[buf] + (kk + tg) * BS + wn + j * 8 + g;
        bf[j][0] = p[0];
        bf[j][1] = p[4 * BS];
      }
      #pragma unroll
      for (int i = 0; i < MI; ++i)
        #pragma unroll
        for (int j = 0; j < NI; ++j)
          mma_tf32(c[i][j], af[i][0], af[i][1], af[i][2], af[i][3],
                   bf[j][0], bf[j][1]);
    }

    if (more) {
      int nb = buf ^ 1;
      uint32_t* as = As[nb] + arow * AS + akh;
      as[0]=f2tf(av0.x); as[1]=f2tf(av0.y); as[2]=f2tf(av0.z); as[3]=f2tf(av0.w);
      as[4]=f2tf(av1.x); as[5]=f2tf(av1.y); as[6]=f2tf(av1.z); as[7]=f2tf(av1.w);
      #pragma unroll
      for (int j = 0; j < BF4; ++j) {
        uint32_t* bs = Bs[nb] + brow[j] * BS + bcol[j];
        bs[0]=f2tf(bv[j].x); bs[1]=f2tf(bv[j].y); bs[2]=f2tf(bv[j].z); bs[3]=f2tf(bv[j].w);
      }
    }
    __syncthreads();
  }

  #pragma unroll
  for (int i = 0; i < MI; ++i) {
    int r0 = bm + wm + i * 16 + g;
    #pragma unroll
    for (int j = 0; j < NI; ++j) {
      int col = bn + wn + j * 8 + tg * 2;
      float b0 = bias ? bias[col] : 0.f;
      float b1 = bias ? bias[col + 1] : 0.f;
      float2 v0 = {c[i][j][0] + b0, c[i][j][1] + b1};
      float2 v1 = {c[i][j][2] + b0, c[i][j][3] + b1};
      *(float2*)&C[(size_t)r0 * N + col] = v0;
      *(float2*)&C[(size_t)(r0 + 8) * N + col] = v1;
    }
  }
}

// =================================================================
// Fused attention per (b, h, 64-row n-tile), tf32 mma for QK^T and PV
// =================================================================
#define QS_OFF  0
#define KS_OFF  (64 * 68)
#define VT_OFF  (KS_OFF + 256 * 68)
#define PS_OFF  (VT_OFF + 64 * 264)
#define ATTN_SMEM_WORDS (PS_OFF + 64 * 260)
#define ATTN_SMEM_BYTES (ATTN_SMEM_WORDS * 4)

__global__ __launch_bounds__(256, 1) void attn_kernel() {
  extern __shared__ uint32_t sm[];
  uint32_t* Qs = sm + QS_OFF;     // [n][d]  stride 68
  uint32_t* Ks = sm + KS_OFF;     // [m][d]  stride 68
  uint32_t* Vt = sm + VT_OFF;     // [d][m]  stride 264
  float*    Ps = (float*)(sm + PS_OFF);  // [n][m] stride 260
  uint32_t* PsU = sm + PS_OFF;

  int t = threadIdx.x;
  int b = blockIdx.y >> 3, h = blockIdx.y & 7;
  int n0 = blockIdx.x * 64;
  int w = t >> 5, l = t & 31;
  int g = l >> 2, tg = l & 3;

  const float* qkvb = g_qkv + (size_t)b * NSEQ * QKV3 + h * DH;

  {
    int c16 = t & 15, r16 = t >> 4;
    int d0 = c16 * 4;
    #pragma unroll
    for (int i = 0; i < 16; ++i) {
      int m = r16 + i * 16;
      const float* rowp = qkvb + (size_t)m * QKV3;
      float4 k4 = *(const float4*)(rowp + DIMC + d0);
      uint4 ku = {f2tf(k4.x), f2tf(k4.y), f2tf(k4.z), f2tf(k4.w)};
      *(uint4*)&Ks[m * 68 + d0] = ku;
      float4 v4 = *(const float4*)(rowp + 2 * DIMC + d0);
      Vt[(d0 + 0) * 264 + m] = f2tf(v4.x);
      Vt[(d0 + 1) * 264 + m] = f2tf(v4.y);
      Vt[(d0 + 2) * 264 + m] = f2tf(v4.z);
      Vt[(d0 + 3) * 264 + m] = f2tf(v4.w);
    }
    #pragma unroll
    for (int i = 0; i < 4; ++i) {
      int n = r16 + i * 16;
      const float* rowp = qkvb + (size_t)(n0 + n) * QKV3;
      float4 q4 = *(const float4*)(rowp + d0);
      uint4 qu = {f2tf(q4.x), f2tf(q4.y), f2tf(q4.z), f2tf(q4.w)};
      *(uint4*)&Qs[n * 68 + d0] = qu;
    }
  }
  __syncthreads();

  // scores S[64][256] = Q @ K^T ; warp tile 32x64
  {
    int wm = (w >> 2) * 32;
    int wnn = (w & 3) * 64;
    float s[2][8][4];
    #pragma unroll
    for (int i = 0; i < 2; ++i)
      #pragma unroll
      for (int j = 0; j < 8; ++j)
        #pragma unroll
        for (int q = 0; q < 4; ++q) s[i][j][q] = 0.f;

    #pragma unroll
    for (int kk = 0; kk < 64; kk += 8) {
      uint32_t a[2][4], bf[8][2];
      #pragma unroll
      for (int i = 0; i < 2; ++i) {
        int r0 = wm + i * 16;
        a[i][0] = Qs[(r0 + g) * 68 + kk + tg];
        a[i][1] = Qs[(r0 + g + 8) * 68 + kk + tg];
        a[i][2] = Qs[(r0 + g) * 68 + kk + tg + 4];
        a[i][3] = Qs[(r0 + g + 8) * 68 + kk + tg + 4];
      }
      #pragma unroll
      for (int j = 0; j < 8; ++j) {
        int m0 = wnn + j * 8;
        bf[j][0] = Ks[(m0 + g) * 68 + kk + tg];
        bf[j][1] = Ks[(m0 + g) * 68 + kk + tg + 4];
      }
      #pragma unroll
      for (int i = 0; i < 2; ++i)
        #pragma unroll
        for (int j = 0; j < 8; ++j)
          mma_tf32(s[i][j], a[i][0], a[i][1], a[i][2], a[i][3],
                   bf[j][0], bf[j][1]);
    }
    #pragma unroll
    for (int i = 0; i < 2; ++i) {
      int r0 = wm + i * 16 + g;
      #pragma unroll
      for (int j = 0; j < 8; ++j) {
        int cc = wnn + j * 8 + tg * 2;
        Ps[r0 * 260 + cc]           = s[i][j][0] * SCALE;
        Ps[r0 * 260 + cc + 1]       = s[i][j][1] * SCALE;
        Ps[(r0 + 8) * 260 + cc]     = s[i][j][2] * SCALE;
        Ps[(r0 + 8) * 260 + cc + 1] = s[i][j][3] * SCALE;
      }
    }
  }
  __syncthreads();

  // softmax; fp32 attn -> g_attn, tf32 bits -> Ps in place
  {
    #pragma unroll
    for (int r = 0; r < 8; ++r) {
      int n = w * 8 + r;
      float* row = &Ps[n * 260];
      float vals[8];
      float vmax = -1e30f;
      #pragma unroll
      for (int i = 0; i < 8; ++i) {
        vals[i] = row[l + i * 32];
        vmax = fmaxf(vmax, vals[i]);
      }
      #pragma unroll
      for (int o = 16; o; o >>= 1)
        vmax = fmaxf(vmax, __shfl_xor_sync(0xffffffffu, vmax, o));
      float ssum = 0.f;
      #pragma unroll
      for (int i = 0; i < 8; ++i) { vals[i] = __expf(vals[i] - vmax); ssum += vals[i]; }
      #pragma unroll
      for (int o = 16; o; o >>= 1) ssum += __shfl_xor_sync(0xffffffffu, ssum, o);
      float inv = 1.f / ssum;
      float* gA = &g_attn[((size_t)(b * 8 + h) * 256 + n0 + n) * 256];
      #pragma unroll
      for (int i = 0; i < 8; ++i) {
        float a = vals[i] * inv;
        gA[l + i * 32] = a;
        PsU[n * 260 + l + i * 32] = f2tf(a);
      }
    }
  }
  __syncthreads();

  // O[64][64] = P @ V ; warp tile 32x16
  {
    int wm = (w >> 2) * 32;
    int wd = (w & 3) * 16;
    float oc[2][2][4];
    #pragma unroll
    for (int i = 0; i < 2; ++i)
      #pragma unroll
      for (int j = 0; j < 2; ++j)
        #pragma unroll
        for (int q = 0; q < 4; ++q) oc[i][j][q] = 0.f;

    #pragma unroll 4
    for (int kk = 0; kk < 256; kk += 8) {
      uint32_t a[2][4], bf[2][2];
      #pragma unroll
      for (int i = 0; i < 2; ++i) {
        int r0 = wm + i * 16;
        a[i][0] = PsU[(r0 + g) * 260 + kk + tg];
        a[i][1] = PsU[(r0 + g + 8) * 260 + kk + tg];
        a[i][2] = PsU[(r0 + g) * 260 + kk + tg + 4];
        a[i][3] = PsU[(r0 + g + 8) * 260 + kk + tg + 4];
      }
      #pragma unroll
      for (int j = 0; j < 2; ++j) {
        int d0 = wd + j * 8;
        bf[j][0] = Vt[(d0 + g) * 264 + kk + tg];
        bf[j][1] = Vt[(d0 + g) * 264 + kk + tg + 4];
      }
      #pragma unroll
      for (int i = 0; i < 2; ++i)
        #pragma unroll
        for (int j = 0; j < 2; ++j)
          mma_tf32(oc[i][j], a[i][0], a[i][1], a[i][2], a[i][3],
                   bf[j][0], bf[j][1]);
    }
    #pragma unroll
    for (int i = 0; i < 2; ++i) {
      int n = n0 + wm + i * 16 + g;
      #pragma unroll
      for (int j = 0; j < 2; ++j) {
        int dd = h * 64 + wd + j * 8 + tg * 2;
        float2 v0 = {oc[i][j][0], oc[i][j][1]};
        float2 v1 = {oc[i][j][2], oc[i][j][3]};
        *(float2*)&g_o[(size_t)(b * 256 + n) * 512 + dd] = v0;
        *(float2*)&g_o[(size_t)(b * 256 + n + 8) * 512 + dd] = v1;
      }
    }
  }
}

// =================================================================
// rpos v2: out2[b,h,n,d] += Σ_m attn[b,h,n,m] * T[idx[n,m], h*64+d]
// 8-deep software-pipelined gather (MLP 8)
// =================================================================
__global__ __launch_bounds__(256) void rpos_kernel(
    const float* __restrict__ table, const int* __restrict__ idx_map) {
  int n = blockIdx.x, h = blockIdx.y;
  __shared__ float sA[8][256];
  __shared__ int   sIdx[256];
  __shared__ float sPart[8][8][64];  // [warp][b][d]

  int t = threadIdx.x;
  sIdx[t] = idx_map[n * 256 + t];
  #pragma unroll
  for (int b = 0; b < 8; ++b)
    sA[b][t] = g_attn[((size_t)(b * 8 + h) * 256 + n) * 256 + t];
  __syncthreads();

  int w = t >> 5, l = t & 31;
  int base = w * 32;
  float accx[8], accy[8];
  #pragma unroll
  for (int b = 0; b < 8; ++b) { accx[b] = 0.f; accy[b] = 0.f; }

  const float* tb = table + h * DH + 2 * l;

  float2 buf[8];
  #pragma unroll
  for (int i = 0; i < 8; ++i)
    buf[i] = *(const float2*)&tb[(size_t)sIdx[base + i] * DIMC];

  #pragma unroll
  for (int mm = 0; mm < 32; ++mm) {
    float2 tv = buf[mm & 7];
    if (mm + 8 < 32)
      buf[mm & 7] = *(const float2*)&tb[(size_t)sIdx[base + mm + 8] * DIMC];
    #pragma unroll
    for (int b = 0; b < 8; ++b) {
      float a = sA[b][base + mm];
      accx[b] += a * tv.x;
      accy[b] += a * tv.y;
    }
  }

  #pragma unroll
  for (int b = 0; b < 8; ++b) {
    sPart[w][b][2 * l]     = accx[b];
    sPart[w][b][2 * l + 1] = accy[b];
  }
  __syncthreads();

  #pragma unroll
  for (int o = t; o < 512; o += 256) {
    int b = o >> 6, d = o & 63;
    float s2 = 0.f;
    #pragma unroll
    for (int w2 = 0; w2 < 8; ++w2) s2 += sPart[w2][b][d];
    g_o[(size_t)(b * 256 + n) * 512 + h * 64 + d] += s2;
  }
}

// =================================================================
extern "C" void kernel_launch(void* const* d_in, const int* in_sizes, int n_in,
                              void* d_out, int out_size) {
  const float* x      = (const float*)d_in[0];
  const float* ln_g   = (const float*)d_in[1];
  const float* ln_b   = (const float*)d_in[2];
  const float* w_qkv  = (const float*)d_in[3];
  const float* table  = (const float*)d_in[4];
  const float* w_out  = (const float*)d_in[5];
  const float* b_out  = (const float*)d_in[6];
  const int*   idxmap = (const int*)d_in[7];
  float* out = (float*)d_out;

  cudaFuncSetAttribute(attn_kernel, cudaFuncAttributeMaxDynamicSharedMemorySize,
                       ATTN_SMEM_BYTES);

  void *p_xn, *p_qkv, *p_o;
  cudaGetSymbolAddress(&p_xn, g_xn);
  cudaGetSymbolAddress(&p_qkv, g_qkv);
  cudaGetSymbolAddress(&p_o, g_o);

  // 1. LayerNorm
  ln_kernel<<<NTOK, 256>>>(x, ln_g, ln_b);

  // 2. qkv = xn @ w_qkv   (2048 x 1536 x 512), BN=128
  gemm_tf32<128, 2, 4><<<dim3(QKV3 / 128, NTOK / 128), 256>>>(
      (const float*)p_xn, w_qkv, nullptr, (float*)p_qkv, NTOK, QKV3, DIMC);

  // 3. attention (scores, softmax, attn·V) on tensor cores
  attn_kernel<<<dim3(4, NB * NHEADS), 256, ATTN_SMEM_BYTES>>>();

  // 4. relative-position contribution (pipelined gather)
  rpos_kernel<<<dim3(NSEQ, NHEADS), 256>>>(table, idxmap);

  // 5. out = g_o @ w_out + b_out   (2048 x 512 x 512), BN=64 -> 128 blocks
  gemm_tf32<64, 4, 2><<<dim3(DIMC / 64, NTOK / 128), 256>>>(
      (const float*)p_o, w_out, b_out, out, NTOK, DIMC, DIMC);
}